// round 8
// baseline (speedup 1.0000x reference)
#include <cuda_runtime.h>

// Problem-fixed shapes (setup_inputs): R=4000, C=20, K=3, H=W=1024, h=w=128.
#define HH 1024
#define WW 1024
#define CC 20
#define hh 128
#define ww 128
#define C1 21      // refine_result last dim = C+1
#define EPSF 1e-6f
#define NSEG 64
#define SEGH 16                 // rows per segment
#define MAXB 16384              // events per (c,seg) bucket; hard max = 4*R = 16000
#define TB   256                // k_B threads
#define GCOL 4                  // columns per thread in k_B (256 thr * 4 = 1024)
#define ECH  2048               // k_B smem event chunk (16 KB)

// Static scratch (no runtime allocation).
// Event: .x = x | (y_local<<10)  (y_local < 16), .y = float bits of +-s.
__device__ int2  g_ev [CC][NSEG][MAXB];     // unsorted events
__device__ int2  g_evs[CC][NSEG][MAXB];     // row-sorted events
__device__ int   g_cnt[CC][NSEG];           // bucket sizes
__device__ float g_seg[CC][NSEG][WW];       // per-segment column-sum PREFIX over x
__device__ float g_Rm[CC][hh][ww];          // sampled integral-image values
__device__ int   g_minb[CC];                // per-channel min of M (float bits)
__device__ int   g_maxb[CC];                // per-channel max of M (float bits)

__device__ __forceinline__ void atomicMinF(int* addr, float v) {
    int old = *addr;
    while (__int_as_float(old) > v) {
        int assumed = old;
        old = atomicCAS(addr, assumed, __float_as_int(v));
        if (old == assumed) break;
    }
}
__device__ __forceinline__ void atomicMaxF(int* addr, float v) {
    int old = *addr;
    while (__int_as_float(old) < v) {
        int assumed = old;
        old = atomicCAS(addr, assumed, __float_as_int(v));
        if (old == assumed) break;
    }
}

// ---------------------------------------------------------------------------
// 0) Reset counters + min/max + output scalar. One block.
__global__ void k_zero(float* __restrict__ out) {
    int t = threadIdx.x;
    if (t == 0) out[0] = 0.f;
    for (int i = t; i < CC * NSEG; i += 1024) ((int*)g_cnt)[i] = 0;
    if (t < CC) {
        g_minb[t] = __float_as_int(3.4e38f);
        g_maxb[t] = __float_as_int(-3.4e38f);
    }
}

// ---------------------------------------------------------------------------
// 1) Scores + sparse event emission. grid (R/256, CC); invalid channels exit.
__device__ __forceinline__ void emit_row(int c, int y, int x1, float s1, int x2, float s2) {
    if (y >= HH) return;                   // reference clips row H away via M[:H]
    int seg = y >> 4, yl = y & (SEGH - 1);
    int2 e1 = make_int2(x1 | (yl << 10), __float_as_int(s1));
    if (x2 < WW) {
        int idx = atomicAdd(&g_cnt[c][seg], 2);
        g_ev[c][seg][idx]     = e1;
        g_ev[c][seg][idx + 1] = make_int2(x2 | (yl << 10), __float_as_int(s2));
    } else {
        int idx = atomicAdd(&g_cnt[c][seg], 1);
        g_ev[c][seg][idx] = e1;
    }
}

__global__ void k_scatter(const float* __restrict__ refine,
                          const float* __restrict__ rois,
                          const int*   __restrict__ labels,
                          int R) {
    int c = blockIdx.y;
    if (labels[c] != 1) return;            // scores *= vmf
    int r = blockIdx.x * blockDim.x + threadIdx.x;
    if (r >= R) return;
    int base = r * C1 + c + 1;             // avg[:,1:]
    float s = (refine[base] + refine[R * C1 + base] + refine[2 * R * C1 + base]) * (1.0f / 3.0f);
    if (s < 0.3f) return;                  // SCORE_THRES
    int x1 = (int)rois[r * 5 + 1];
    int y1 = (int)rois[r * 5 + 2];
    int x2 = (int)rois[r * 5 + 3];
    int y2 = (int)rois[r * 5 + 4];
    // M(y,x) = sum s * [y1<=y<y2] * [x1<=x<x2]
    emit_row(c, y1, x1,  s, x2, -s);
    emit_row(c, y2, x1, -s, x2,  s);
}

// ---------------------------------------------------------------------------
// 2) Per bucket: (a) column-sum prefix g_seg (shfl-based scan);
//    (b) counting-sort events by local row into g_evs. grid (NSEG, CC), 1024 thr.
__global__ __launch_bounds__(1024) void k_A(const int* __restrict__ labels) {
    int c = blockIdx.y;
    if (labels[c] != 1) return;
    int seg = blockIdx.x, t = threadIdx.x;
    int lane = t & 31, warp = t >> 5;

    __shared__ float arr[WW];
    __shared__ float wsum[32];
    __shared__ int   cnt[SEGH + 1];
    __shared__ int   cur[SEGH];

    arr[t] = 0.f;
    if (t <= SEGH) cnt[t] = 0;
    __syncthreads();

    int E = g_cnt[c][seg];
    for (int i = t; i < E; i += 1024) {
        int2 e = g_ev[c][seg][i];
        atomicAdd(&arr[e.x & 0x3FF], __int_as_float(e.y));
        atomicAdd(&cnt[(e.x >> 10) + 1], 1);
    }
    __syncthreads();

    if (t == 0) {
        int acc = 0;
        #pragma unroll
        for (int j = 0; j <= SEGH; ++j) { acc += cnt[j]; cnt[j] = acc; }
        #pragma unroll
        for (int j = 0; j < SEGH; ++j) cur[j] = cnt[j];
    }
    // Warp-level inclusive scan of arr[t] (1024 columns).
    float v = arr[t];
    #pragma unroll
    for (int o = 1; o < 32; o <<= 1) {
        float n = __shfl_up_sync(0xFFFFFFFF, v, o);
        if (lane >= o) v += n;
    }
    if (lane == 31) wsum[warp] = v;
    __syncthreads();
    if (warp == 0) {
        float w = wsum[lane];
        #pragma unroll
        for (int o = 1; o < 32; o <<= 1) {
            float n = __shfl_up_sync(0xFFFFFFFF, w, o);
            if (lane >= o) w += n;
        }
        wsum[lane] = w;
    }
    __syncthreads();
    if (warp > 0) v += wsum[warp - 1];
    g_seg[c][seg][t] = v;

    // Place events in row-sorted order (within-row order irrelevant).
    for (int i = t; i < E; i += 1024) {
        int2 e = g_ev[c][seg][i];
        int p = atomicAdd(&cur[e.x >> 10], 1);
        g_evs[c][seg][p] = e;
    }
}

// ---------------------------------------------------------------------------
// 3) Fused column scan from sorted sparse events. 256 threads per bucket,
//    thread owns 4 contiguous columns: run(4t+g) = common + ofs[g].
//    Events cooperatively staged in smem (coalesced), then consumed via LDS
//    broadcast. Base offset = in-block sum of L2-resident g_seg rows.
//    grid (NSEG, CC), 256 thr.
__global__ __launch_bounds__(TB) void k_B(const int* __restrict__ labels) {
    int c = blockIdx.y;
    if (labels[c] != 1) return;
    int seg = blockIdx.x, t = threadIdx.x;

    // Base: sum of segment prefixes above this segment (L2-resident, coalesced).
    float4 a = make_float4(0.f, 0.f, 0.f, 0.f);
    {
        const float4* segp = reinterpret_cast<const float4*>(&g_seg[c][0][0]);
        #pragma unroll 4
        for (int s = 0; s < seg; ++s) {
            float4 r = segp[s * (WW / 4) + t];
            a.x += r.x; a.y += r.y; a.z += r.z; a.w += r.w;
        }
    }
    float ofs[GCOL] = {a.x, a.y, a.z, a.w};

    float common = 0.f;
    float min_ofs = 0.f, max_ofs = 0.f;
    bool dirty = true;
    float mn = 3.4e38f, mx = -3.4e38f;
    int y = 0;

    __shared__ int2 evs[ECH];
    int E = g_cnt[c][seg];
    const int2* evp = &g_evs[c][seg][0];

    for (int base = 0; base < E; base += ECH) {
        int n = min(ECH, E - base);
        for (int i = t; i < n; i += TB) evs[i] = evp[base + i];   // coalesced
        __syncthreads();

        #pragma unroll 4
        for (int i = 0; i < n; ++i) {
            int2 e = evs[i];                     // LDS broadcast, pipelined
            int ey = e.x >> 10;
            int xe = e.x & 0x3FF;
            float se = __int_as_float(e.y);

            if (ey > y) {                        // warp-uniform gap advance (rare)
                if (dirty) {
                    min_ofs = fminf(fminf(ofs[0], ofs[1]), fminf(ofs[2], ofs[3]));
                    max_ofs = fmaxf(fmaxf(ofs[0], ofs[1]), fmaxf(ofs[2], ofs[3]));
                    dirty = false;
                }
                mn = fminf(mn, common + min_ofs);
                mx = fmaxf(mx, common + max_ofs);
                int ys = (y + 7) & ~7;           // sampled local rows: 0 or 8
                if (ys < ey && (t & 1) == 0) {   // column 4t, sampled iff t even
                    float sval = common + ofs[0];
                    for (; ys < ey; ys += 8)
                        g_Rm[c][seg * (SEGH / 8) + (ys >> 3)][t >> 1] = sval;
                }
                y = ey;
            }

            int owner = xe >> 2;
            if (t > owner) {
                common += se;
            } else if (t == owner) {
                int g0 = xe & 3;
                #pragma unroll
                for (int g = 0; g < GCOL; ++g)
                    if (g >= g0) ofs[g] += se;
                dirty = true;
            }
        }
        __syncthreads();
    }

    // Flush remaining rows [y, SEGH).
    if (dirty) {
        min_ofs = fminf(fminf(ofs[0], ofs[1]), fminf(ofs[2], ofs[3]));
        max_ofs = fmaxf(fmaxf(ofs[0], ofs[1]), fmaxf(ofs[2], ofs[3]));
    }
    if (y < SEGH) {
        mn = fminf(mn, common + min_ofs);
        mx = fmaxf(mx, common + max_ofs);
        int ys = (y + 7) & ~7;
        if ((t & 1) == 0) {
            float sval = common + ofs[0];
            for (; ys < SEGH; ys += 8)
                g_Rm[c][seg * (SEGH / 8) + (ys >> 3)][t >> 1] = sval;
        }
    }

    // Block-wide min/max reduce: warp shfl + cross-warp smem.
    int lane = t & 31, warp = t >> 5;
    #pragma unroll
    for (int o = 16; o; o >>= 1) {
        mn = fminf(mn, __shfl_xor_sync(0xFFFFFFFF, mn, o));
        mx = fmaxf(mx, __shfl_xor_sync(0xFFFFFFFF, mx, o));
    }
    __shared__ float rmn[8], rmx[8];
    if (lane == 0) { rmn[warp] = mn; rmx[warp] = mx; }
    __syncthreads();
    if (t == 0) {
        float fmn = rmn[0], fmx = rmx[0];
        #pragma unroll
        for (int wgt = 1; wgt < TB / 32; ++wgt) {
            fmn = fminf(fmn, rmn[wgt]);
            fmx = fmaxf(fmx, rmx[wgt]);
        }
        atomicMinF(&g_minb[c], fmn);
        atomicMaxF(&g_maxb[c], fmx);
    }
}

// ---------------------------------------------------------------------------
// 4) Per-channel loss, normalized and atomically accumulated into out[0].
//    grid (CC), 128 thr.
__global__ void k_loss(const float* __restrict__ blob,
                       const int*   __restrict__ labels,
                       float* __restrict__ out) {
    int c = blockIdx.x, t = threadIdx.x;
    bool valid = (labels[c] == 1);
    const float* B = blob + c * hh * ww;

    float cmax = 0.f;
    #pragma unroll 8
    for (int i = 0; i < hh; ++i) cmax = fmaxf(cmax, B[i * ww + t]);
    float rmax = 0.f;
    #pragma unroll 8
    for (int j = 0; j < ww; ++j) rmax = fmaxf(rmax, B[t * ww + j]);
    cmax = fminf(fmaxf(cmax, EPSF), 1.f - EPSF);
    rmax = fminf(fmaxf(rmax, EPSF), 1.f - EPSF);

    float vx, vy;
    if (valid) {
        float mnv = __int_as_float(g_minb[c]);
        float mxv = __int_as_float(g_maxb[c]);
        float thr = mnv + 0.5f * (mxv - mnv + EPSF);   // normalized >= 0.5
        float scol = -3.4e38f, srow = -3.4e38f;
        #pragma unroll 8
        for (int i = 0; i < hh; ++i) scol = fmaxf(scol, g_Rm[c][i][t]);
        #pragma unroll 8
        for (int j = 0; j < ww; ++j) srow = fmaxf(srow, g_Rm[c][t][j]);
        vx = (scol >= thr) ? -logf(cmax) : 0.f;
        vy = (srow >= thr) ? -logf(rmax) : 0.f;
    } else {
        vx = -logf(1.f - cmax);
        vy = -logf(1.f - rmax);
    }

    __shared__ float sx[128], sy[128];
    sx[t] = vx; sy[t] = vy;
    __syncthreads();
    for (int o = 64; o; o >>= 1) {
        if (t < o) { sx[t] += sx[t + o]; sy[t] += sy[t + o]; }
        __syncthreads();
    }
    if (t == 0) {
        float vc = 0.f;
        for (int k = 0; k < CC; ++k) vc += (labels[k] == 1) ? 1.f : 0.f;
        float nvc = (float)CC - vc;
        float denom = valid ? vc : nvc;
        atomicAdd(out, sx[0] / (denom * (float)ww) + sy[0] / (denom * (float)hh));
    }
}

// ---------------------------------------------------------------------------
extern "C" void kernel_launch(void* const* d_in, const int* in_sizes, int n_in,
                              void* d_out, int out_size) {
    // metadata order: mil_result(unused), refine_result, blob_conv, rois, labels, H, W
    const float* refine = (const float*)d_in[1];
    const float* blob   = (const float*)d_in[2];
    const float* rois   = (const float*)d_in[3];
    const int*   labels = (const int*)  d_in[4];
    int R = in_sizes[3] / 5;
    float* out = (float*)d_out;

    k_zero   <<<1, 1024>>>(out);
    k_scatter<<<dim3((R + 255) / 256, CC), 256>>>(refine, rois, labels, R);
    k_A      <<<dim3(NSEG, CC), 1024>>>(labels);
    k_B      <<<dim3(NSEG, CC), TB>>>(labels);
    k_loss   <<<CC, 128>>>(blob, labels, out);
}

// round 9
// speedup vs baseline: 1.5137x; 1.5137x over previous
#include <cuda_runtime.h>

// Problem-fixed shapes (setup_inputs): R=4000, C=20, K=3, H=W=1024, h=w=128.
#define HH 1024
#define WW 1024
#define CC 20
#define hh 128
#define ww 128
#define C1 21      // refine_result last dim = C+1
#define EPSF 1e-6f
#define NSEG 64
#define SEGH 16                 // rows per segment
#define MAXB 16384              // events per (c,seg) bucket; hard max = 4*R = 16000
#define PROWS 8                 // rows per smem phase in k_B (2 phases)

// Static scratch (no runtime allocation).
// Event: .x = x | (y_local<<10)  (y_local < 16), .y = float bits of +-s.
__device__ int2  g_ev [CC][NSEG][MAXB];     // events (order irrelevant)
__device__ int   g_cnt[CC][NSEG];           // bucket sizes
__device__ float g_seg[CC][NSEG][WW];       // per-segment column-sum PREFIX over x
__device__ float g_Rm[CC][hh][ww];          // sampled integral-image values
__device__ int   g_minb[CC];                // per-channel min of M (float bits)
__device__ int   g_maxb[CC];                // per-channel max of M (float bits)

__device__ __forceinline__ void atomicMinF(int* addr, float v) {
    int old = *addr;
    while (__int_as_float(old) > v) {
        int assumed = old;
        old = atomicCAS(addr, assumed, __float_as_int(v));
        if (old == assumed) break;
    }
}
__device__ __forceinline__ void atomicMaxF(int* addr, float v) {
    int old = *addr;
    while (__int_as_float(old) < v) {
        int assumed = old;
        old = atomicCAS(addr, assumed, __float_as_int(v));
        if (old == assumed) break;
    }
}

// ---------------------------------------------------------------------------
// 0) Reset counters + min/max + output scalar. One block.
__global__ void k_zero(float* __restrict__ out) {
    int t = threadIdx.x;
    if (t == 0) out[0] = 0.f;
    for (int i = t; i < CC * NSEG; i += 1024) ((int*)g_cnt)[i] = 0;
    if (t < CC) {
        g_minb[t] = __float_as_int(3.4e38f);
        g_maxb[t] = __float_as_int(-3.4e38f);
    }
}

// ---------------------------------------------------------------------------
// 1) Scores + sparse event emission. grid (R/256, CC); invalid channels exit.
__device__ __forceinline__ void emit_row(int c, int y, int x1, float s1, int x2, float s2) {
    if (y >= HH) return;                   // reference clips row H away via M[:H]
    int seg = y >> 4, yl = y & (SEGH - 1);
    int2 e1 = make_int2(x1 | (yl << 10), __float_as_int(s1));
    if (x2 < WW) {
        int idx = atomicAdd(&g_cnt[c][seg], 2);
        g_ev[c][seg][idx]     = e1;
        g_ev[c][seg][idx + 1] = make_int2(x2 | (yl << 10), __float_as_int(s2));
    } else {
        int idx = atomicAdd(&g_cnt[c][seg], 1);
        g_ev[c][seg][idx] = e1;
    }
}

__global__ void k_scatter(const float* __restrict__ refine,
                          const float* __restrict__ rois,
                          const int*   __restrict__ labels,
                          int R) {
    int c = blockIdx.y;
    if (labels[c] != 1) return;            // scores *= vmf
    int r = blockIdx.x * blockDim.x + threadIdx.x;
    if (r >= R) return;
    int base = r * C1 + c + 1;             // avg[:,1:]
    float s = (refine[base] + refine[R * C1 + base] + refine[2 * R * C1 + base]) * (1.0f / 3.0f);
    if (s < 0.3f) return;                  // SCORE_THRES
    int x1 = (int)rois[r * 5 + 1];
    int y1 = (int)rois[r * 5 + 2];
    int x2 = (int)rois[r * 5 + 3];
    int y2 = (int)rois[r * 5 + 4];
    // M(y,x) = sum s * [y1<=y<y2] * [x1<=x<x2]
    emit_row(c, y1, x1,  s, x2, -s);
    emit_row(c, y2, x1, -s, x2,  s);
}

// ---------------------------------------------------------------------------
// 2) Per bucket: column-sum prefix g_seg[c][seg][x] (smem scatter + shfl scan).
//    grid (NSEG, CC), 1024 thr.
__global__ __launch_bounds__(1024) void k_A(const int* __restrict__ labels) {
    int c = blockIdx.y;
    if (labels[c] != 1) return;
    int seg = blockIdx.x, t = threadIdx.x;
    int lane = t & 31, warp = t >> 5;

    __shared__ float arr[WW];
    __shared__ float wsum[32];

    arr[t] = 0.f;
    __syncthreads();

    int E = g_cnt[c][seg];
    for (int i = t; i < E; i += 1024) {
        int2 e = g_ev[c][seg][i];
        atomicAdd(&arr[e.x & 0x3FF], __int_as_float(e.y));
    }
    __syncthreads();

    // Warp-level inclusive scan of arr[t] (1024 columns).
    float v = arr[t];
    #pragma unroll
    for (int o = 1; o < 32; o <<= 1) {
        float n = __shfl_up_sync(0xFFFFFFFF, v, o);
        if (lane >= o) v += n;
    }
    if (lane == 31) wsum[warp] = v;
    __syncthreads();
    if (warp == 0) {
        float w = wsum[lane];
        #pragma unroll
        for (int o = 1; o < 32; o <<= 1) {
            float n = __shfl_up_sync(0xFFFFFFFF, w, o);
            if (lane >= o) w += n;
        }
        wsum[lane] = w;
    }
    __syncthreads();
    if (warp > 0) v += wsum[warp - 1];
    g_seg[c][seg][t] = v;
}

// ---------------------------------------------------------------------------
// 3) Column scan via smem difference-array + per-row parallel prefix.
//    Thread = one column. Bucket's 16 rows processed in 2 phases of 8:
//    zero diff -> parallel event scatter -> per-row shfl scan -> run += P.
//    Branch-free and event-count independent per column.
//    grid (NSEG, CC), 1024 thr.
__global__ __launch_bounds__(1024) void k_B(const int* __restrict__ labels) {
    int c = blockIdx.y;
    if (labels[c] != 1) return;
    int seg = blockIdx.x, x = threadIdx.x;
    int lane = x & 31, warp = x >> 5;

    __shared__ float diff[PROWS][WW];    // 32 KB
    __shared__ float wsum[PROWS][32];    // per-row warp sums
    __shared__ float redmn[32], redmx[32];

    // Base: sum of segment prefixes above this segment (L2-resident, coalesced).
    float run = 0.f;
    {
        int s = 0;
        for (; s + 8 <= seg; s += 8) {   // 8 independent loads per batch (MLP)
            float v0 = g_seg[c][s + 0][x], v1 = g_seg[c][s + 1][x];
            float v2 = g_seg[c][s + 2][x], v3 = g_seg[c][s + 3][x];
            float v4 = g_seg[c][s + 4][x], v5 = g_seg[c][s + 5][x];
            float v6 = g_seg[c][s + 6][x], v7 = g_seg[c][s + 7][x];
            run += ((v0 + v1) + (v2 + v3)) + ((v4 + v5) + (v6 + v7));
        }
        for (; s < seg; ++s) run += g_seg[c][s][x];
    }

    float mn = 3.4e38f, mx = -3.4e38f;
    int E = g_cnt[c][seg];

    #pragma unroll
    for (int p = 0; p < SEGH / PROWS; ++p) {
        // Zero phase diff rows.
        #pragma unroll
        for (int r = 0; r < PROWS; ++r) diff[r][x] = 0.f;
        __syncthreads();

        // Parallel event scatter (order irrelevant).
        for (int i = x; i < E; i += 1024) {
            int2 e = g_ev[c][seg][i];
            int yl = e.x >> 10;
            if ((yl >> 3) == p)
                atomicAdd(&diff[yl & 7][e.x & 0x3FF], __int_as_float(e.y));
        }
        __syncthreads();

        // Per-row warp scans (all rows, high ILP), store warp sums.
        float varr[PROWS];
        #pragma unroll
        for (int r = 0; r < PROWS; ++r) {
            float v = diff[r][x];
            #pragma unroll
            for (int o = 1; o < 32; o <<= 1) {
                float n = __shfl_up_sync(0xFFFFFFFF, v, o);
                if (lane >= o) v += n;
            }
            varr[r] = v;
            if (lane == 31) wsum[p & 1 ? r : r][r == r ? warp : warp] = v;  // plain store
        }
        // (the line above is just wsum[r][warp] = v; keep simple)
        __syncthreads();

        // Cross-warp combine + accumulate rows in order.
        #pragma unroll
        for (int r = 0; r < PROWS; ++r) {
            float w = wsum[r][lane];
            #pragma unroll
            for (int o = 1; o < 32; o <<= 1) {
                float n = __shfl_up_sync(0xFFFFFFFF, w, o);
                if (lane >= o) w += n;
            }
            float wexcl = __shfl_sync(0xFFFFFFFF, w, (warp == 0) ? 0 : warp - 1);
            if (warp == 0) wexcl = 0.f;
            float P = varr[r] + wexcl;       // row's full column prefix
            run += P;                        // M at row seg*16 + p*8 + r
            mn = fminf(mn, run);
            mx = fmaxf(mx, run);
            if (r == 0 && (x & 7) == 0)      // sampled row (multiple of 8)
                g_Rm[c][seg * 2 + p][x >> 3] = run;
        }
        __syncthreads();                     // wsum/diff reuse next phase
    }

    // Block-wide min/max reduce.
    #pragma unroll
    for (int o = 16; o; o >>= 1) {
        mn = fminf(mn, __shfl_xor_sync(0xFFFFFFFF, mn, o));
        mx = fmaxf(mx, __shfl_xor_sync(0xFFFFFFFF, mx, o));
    }
    if (lane == 0) { redmn[warp] = mn; redmx[warp] = mx; }
    __syncthreads();
    if (warp == 0) {
        float fmn = redmn[lane], fmx = redmx[lane];
        #pragma unroll
        for (int o = 16; o; o >>= 1) {
            fmn = fminf(fmn, __shfl_xor_sync(0xFFFFFFFF, fmn, o));
            fmx = fmaxf(fmx, __shfl_xor_sync(0xFFFFFFFF, fmx, o));
        }
        if (lane == 0) {
            atomicMinF(&g_minb[c], fmn);
            atomicMaxF(&g_maxb[c], fmx);
        }
    }
}

// ---------------------------------------------------------------------------
// 4) Per-channel loss, normalized and atomically accumulated into out[0].
//    grid (CC), 128 thr.
__global__ void k_loss(const float* __restrict__ blob,
                       const int*   __restrict__ labels,
                       float* __restrict__ out) {
    int c = blockIdx.x, t = threadIdx.x;
    bool valid = (labels[c] == 1);
    const float* B = blob + c * hh * ww;

    float cmax = 0.f;
    for (int i = 0; i < hh; ++i) cmax = fmaxf(cmax, B[i * ww + t]);
    float rmax = 0.f;
    for (int j = 0; j < ww; ++j) rmax = fmaxf(rmax, B[t * ww + j]);
    cmax = fminf(fmaxf(cmax, EPSF), 1.f - EPSF);
    rmax = fminf(fmaxf(rmax, EPSF), 1.f - EPSF);

    float vx, vy;
    if (valid) {
        float mnv = __int_as_float(g_minb[c]);
        float mxv = __int_as_float(g_maxb[c]);
        float thr = mnv + 0.5f * (mxv - mnv + EPSF);   // normalized >= 0.5
        float scol = -3.4e38f, srow = -3.4e38f;
        for (int i = 0; i < hh; ++i) scol = fmaxf(scol, g_Rm[c][i][t]);
        for (int j = 0; j < ww; ++j) srow = fmaxf(srow, g_Rm[c][t][j]);
        vx = (scol >= thr) ? -logf(cmax) : 0.f;
        vy = (srow >= thr) ? -logf(rmax) : 0.f;
    } else {
        vx = -logf(1.f - cmax);
        vy = -logf(1.f - rmax);
    }

    __shared__ float sx[128], sy[128];
    sx[t] = vx; sy[t] = vy;
    __syncthreads();
    for (int o = 64; o; o >>= 1) {
        if (t < o) { sx[t] += sx[t + o]; sy[t] += sy[t + o]; }
        __syncthreads();
    }
    if (t == 0) {
        float vc = 0.f;
        for (int k = 0; k < CC; ++k) vc += (labels[k] == 1) ? 1.f : 0.f;
        float nvc = (float)CC - vc;
        float denom = valid ? vc : nvc;
        atomicAdd(out, sx[0] / (denom * (float)ww) + sy[0] / (denom * (float)hh));
    }
}

// ---------------------------------------------------------------------------
extern "C" void kernel_launch(void* const* d_in, const int* in_sizes, int n_in,
                              void* d_out, int out_size) {
    // metadata order: mil_result(unused), refine_result, blob_conv, rois, labels, H, W
    const float* refine = (const float*)d_in[1];
    const float* blob   = (const float*)d_in[2];
    const float* rois   = (const float*)d_in[3];
    const int*   labels = (const int*)  d_in[4];
    int R = in_sizes[3] / 5;
    float* out = (float*)d_out;

    k_zero   <<<1, 1024>>>(out);
    k_scatter<<<dim3((R + 255) / 256, CC), 256>>>(refine, rois, labels, R);
    k_A      <<<dim3(NSEG, CC), 1024>>>(labels);
    k_B      <<<dim3(NSEG, CC), 1024>>>(labels);
    k_loss   <<<CC, 128>>>(blob, labels, out);
}